// round 10
// baseline (speedup 1.0000x reference)
#include <cuda_runtime.h>
#include <math.h>

#define NB 13
#define NW 118
#define MAXW 12
#define NPTS 2048
#define TAB_STRIDE (NPTS + 1)
#define XMIN (-8.0f)
#define XSPAN 16.0f
#define INV_H ((float)NPTS / XSPAN)   /* 128 */
#define H_STEP (XSPAN / (float)NPTS)

// tokens = 32*4096 = 131072 ; per block 64 tokens, 256 threads (4 thr/token)
#define TOK_PER_BLK 64
#define THREADS 256
#define NBLK 2048
#define TILE_FLOATS (TOK_PER_BLK * NW)        /* 7552 */
#define OUT_PER_BLK (TOK_PER_BLK * NB)        /* 832 */
#define SMEM_FLOATS (TILE_FLOATS + OUT_PER_BLK + NB * MAXW)  /* 8540 -> 34.2KB */

// build kernel: 64 entries/block, 4 lanes per entry
#define ENT_PER_BLK 64
#define BUILD_THREADS 256

// Compile-time ragged structure (fixed by the problem)
__device__ constexpr int K_START[NB] = {5, 14, 23, 32, 41, 50, 59, 68, 77, 86, 95, 107, 115};
__device__ constexpr int K_LEN[NB]   = {9, 9, 9, 9, 9, 9, 9, 9, 9, 9, 12, 8, 3};

// Scratch (__device__ globals are the allowed scratch mechanism)
__device__ float g_table[NB * TAB_STRIDE];
__device__ float g_wts[NB * MAXW];

__device__ __forceinline__ float gelu_erf(float x) {
    return 0.5f * x * (1.0f + erff(x * 0.70710678118654752f));
}

// ---------------------------------------------------------------------------
// Kernel 1: build per-body tables. 4 lanes cooperate per table entry.
// grid = (ceil(TAB_STRIDE/64), 13), block = 256
// ---------------------------------------------------------------------------
__global__ __launch_bounds__(BUILD_THREADS) void build_table_kernel(
    const float* __restrict__ agg_logits,
    const float* __restrict__ W1, const float* __restrict__ b1,
    const float* __restrict__ W2, const float* __restrict__ b2,
    const float* __restrict__ W3, const float* __restrict__ b3,
    const float* __restrict__ W4, const float* __restrict__ b4)
{
    const int c   = blockIdx.y;
    const int tid = threadIdx.x;

    // Fused softmax: block (0,0), lanes 0..12 compute g_wts once.
    if (blockIdx.x == 0 && c == 0 && tid < NB) {
        const int cc = tid;
        const int L = K_LEN[cc];
        float tmp[MAXW];
        float mx = -1e30f;
        for (int k = 0; k < L; k++) {
            tmp[k] = agg_logits[cc * MAXW + k];
            mx = fmaxf(mx, tmp[k]);
        }
        float s = 0.0f;
        for (int k = 0; k < L; k++) { tmp[k] = expf(tmp[k] - mx); s += tmp[k]; }
        const float inv = 1.0f / s;
        for (int k = 0; k < MAXW; k++)
            g_wts[cc * MAXW + k] = (k < L) ? tmp[k] * inv : 0.0f;
    }

    __shared__ float sW1[32], sB1[32], sB2[64], sB3[32], sW4[32];
    __shared__ float sW2[32 * 64];   // [i][o], o contiguous
    __shared__ float sW3[64 * 32];   // [i][o], o contiguous
    __shared__ float sB4;

    for (int i = tid; i < 2048; i += BUILD_THREADS) {
        sW2[i] = W2[c * 2048 + i];
        sW3[i] = W3[c * 2048 + i];
    }
    if (tid < 32) {
        sW1[tid] = W1[c * 32 + tid];
        sB1[tid] = b1[c * 32 + tid];
        sB3[tid] = b3[c * 32 + tid];
        sW4[tid] = W4[c * 32 + tid];
    }
    if (tid < 64) sB2[tid] = b2[c * 64 + tid];
    if (tid == 0) sB4 = b4[c];
    __syncthreads();

    const int ent_local = tid >> 2;        // 0..63
    const int q         = tid & 3;         // lane-in-quad
    const int lane      = tid & 31;
    const int qbase     = lane & ~3;       // quad base lane in warp
    const int i_raw     = blockIdx.x * ENT_PER_BLK + ent_local;
    const int i         = (i_raw <= NPTS) ? i_raw : NPTS;   // clamp, store-guarded

    const float x = XMIN + H_STEP * (float)i;

    // h1: each lane computes 8 of 32 (j = q*8 .. q*8+7)
    float h1loc[8];
#pragma unroll
    for (int jj = 0; jj < 8; jj++)
        h1loc[jj] = gelu_erf(fmaf(x, sW1[q * 8 + jj], sB1[q * 8 + jj]));

    // h2: each lane owns 16 of 64 columns (col0 = q*16); h1 shared via shfl
    const int col0 = q * 16;
    float z2[16];
#pragma unroll
    for (int k = 0; k < 16; k++) z2[k] = sB2[col0 + k];

#pragma unroll
    for (int g = 0; g < 4; g++) {
#pragma unroll
        for (int jj = 0; jj < 8; jj++) {
            const float h1v = __shfl_sync(0xffffffffu, h1loc[jj], qbase + g);
            const int j = g * 8 + jj;
#pragma unroll
            for (int k = 0; k < 16; k += 4) {
                const float4 w = *reinterpret_cast<const float4*>(&sW2[j * 64 + col0 + k]);
                z2[k]     = fmaf(h1v, w.x, z2[k]);
                z2[k + 1] = fmaf(h1v, w.y, z2[k + 1]);
                z2[k + 2] = fmaf(h1v, w.z, z2[k + 2]);
                z2[k + 3] = fmaf(h1v, w.w, z2[k + 3]);
            }
        }
    }
    float h2loc[16];
#pragma unroll
    for (int k = 0; k < 16; k++) h2loc[k] = gelu_erf(z2[k]);

    // h3: partial sums over this lane's 16 h2 inputs, all 32 outputs
    float z3[32];
#pragma unroll
    for (int o = 0; o < 32; o++) z3[o] = 0.0f;
#pragma unroll
    for (int jj = 0; jj < 16; jj++) {
        const int j = col0 + jj;
        const float hv = h2loc[jj];
#pragma unroll
        for (int o = 0; o < 32; o += 4) {
            const float4 w = *reinterpret_cast<const float4*>(&sW3[j * 32 + o]);
            z3[o]     = fmaf(hv, w.x, z3[o]);
            z3[o + 1] = fmaf(hv, w.y, z3[o + 1]);
            z3[o + 2] = fmaf(hv, w.z, z3[o + 2]);
            z3[o + 3] = fmaf(hv, w.w, z3[o + 3]);
        }
    }
    // quad butterfly reduce: all lanes end with the full 32 sums
#pragma unroll
    for (int o = 0; o < 32; o++) {
        z3[o] += __shfl_xor_sync(0xffffffffu, z3[o], 1);
        z3[o] += __shfl_xor_sync(0xffffffffu, z3[o], 2);
    }

    // final layer: each lane handles 8 of 32 h3 outputs, then quad-reduce
    float acc = 0.0f;
#pragma unroll
    for (int oo = 0; oo < 8; oo++) {
        const int o = q * 8 + oo;
        const float h3v = gelu_erf(z3[o] + sB3[o]);
        acc = fmaf(h3v, sW4[o], acc);
    }
    acc += __shfl_xor_sync(0xffffffffu, acc, 1);
    acc += __shfl_xor_sync(0xffffffffu, acc, 2);

    if (q == 0 && i_raw <= NPTS)
        g_table[c * TAB_STRIDE + i_raw] = tanhf(acc + sB4);
}

// ---------------------------------------------------------------------------
// Templated per-thread body-range worker (fully unrolled at compile time)
// ---------------------------------------------------------------------------
template<int LO, int HI>
__device__ __forceinline__ void process_bodies(
    const float* __restrict__ x, const float* __restrict__ wts,
    float* __restrict__ so)
{
#pragma unroll
    for (int c = LO; c < HI; c++) {
        float acc = 0.0f;
        const int st = K_START[c];
#pragma unroll
        for (int k = 0; k < K_LEN[c]; k++)
            acc = fmaf(x[st + k], wts[c * MAXW + k], acc);

        float t = (acc - XMIN) * INV_H;
        t = fminf(fmaxf(t, 0.0f), (float)NPTS - 0.001f);
        const int   i0 = (int)t;
        const float fr = t - (float)i0;
        const float* tb = g_table + c * TAB_STRIDE + i0;
        const float v0 = __ldg(tb);
        const float v1 = __ldg(tb + 1);
        so[c] = fmaf(fr, v1 - v0, v0);
    }
}

// ---------------------------------------------------------------------------
// Kernel 2: stream wave_features, ragged weighted sums, table lerp, store.
// grid = 2048, block = 256, dynamic smem = SMEM_FLOATS*4 (34.2KB -> 6 CTA/SM)
// ---------------------------------------------------------------------------
__global__ __launch_bounds__(THREADS) void main_kernel(
    const float* __restrict__ wf,
    float* __restrict__ out)
{
    extern __shared__ float smem[];
    float* sx   = smem;                       // [64 * 118] flat, token-major
    float* sout = smem + TILE_FLOATS;         // [64 * 13]
    float* wts  = sout + OUT_PER_BLK;         // [13 * 12]

    const int tid = threadIdx.x;

    // Coalesced float4 tile load (7552 floats = 1888 float4 per block)
    {
        const float4* g4 = reinterpret_cast<const float4*>(wf) +
                           (size_t)blockIdx.x * (TILE_FLOATS / 4);
        float4* s4 = reinterpret_cast<float4*>(sx);
        for (int i = tid; i < TILE_FLOATS / 4; i += THREADS)
            s4[i] = g4[i];
    }

    // Softmax weights: 156 floats, one pass (THREADS=256 > 156)
    if (tid < NB * MAXW) wts[tid] = g_wts[tid];
    __syncthreads();

    // 4 threads per token: grp selects a compile-time body range
    const int tok = tid & (TOK_PER_BLK - 1);
    const int grp = tid >> 6;
    const float* x = sx + tok * NW;
    float* so = sout + tok * NB;

    switch (grp) {
        case 0: process_bodies<0, 3>(x, wts, so);  break;
        case 1: process_bodies<3, 6>(x, wts, so);  break;
        case 2: process_bodies<6, 9>(x, wts, so);  break;
        default: process_bodies<9, 13>(x, wts, so); break;
    }
    __syncthreads();

    // Coalesced float4 output store: 832 floats = 208 float4 per block
    float4* ob4 = reinterpret_cast<float4*>(out + (size_t)blockIdx.x * OUT_PER_BLK);
    const float4* so4 = reinterpret_cast<const float4*>(sout);
    if (tid < OUT_PER_BLK / 4)
        ob4[tid] = so4[tid];
}

// ---------------------------------------------------------------------------
extern "C" void kernel_launch(void* const* d_in, const int* in_sizes, int n_in,
                              void* d_out, int out_size)
{
    const float* wf  = (const float*)d_in[0];
    const float* lg  = (const float*)d_in[1];
    const float* W1  = (const float*)d_in[2];
    const float* b1  = (const float*)d_in[3];
    const float* W2  = (const float*)d_in[4];
    const float* b2  = (const float*)d_in[5];
    const float* W3  = (const float*)d_in[6];
    const float* b3  = (const float*)d_in[7];
    const float* W4  = (const float*)d_in[8];
    const float* b4  = (const float*)d_in[9];
    float* out = (float*)d_out;

    (void)cudaFuncSetAttribute(main_kernel,
                               cudaFuncAttributeMaxDynamicSharedMemorySize,
                               SMEM_FLOATS * 4);

    dim3 bgrid((TAB_STRIDE + ENT_PER_BLK - 1) / ENT_PER_BLK, NB);
    build_table_kernel<<<bgrid, BUILD_THREADS>>>(lg, W1, b1, W2, b2, W3, b3, W4, b4);

    main_kernel<<<NBLK, THREADS, SMEM_FLOATS * 4>>>(wf, out);

    (void)in_sizes; (void)n_in; (void)out_size;
}

// round 11
// speedup vs baseline: 1.4838x; 1.4838x over previous
#include <cuda_runtime.h>
#include <math.h>

#define NB 13
#define NW 118
#define MAXW 12
#define NPTS 2048
#define TAB_STRIDE (NPTS + 1)
#define XMIN (-8.0f)
#define XSPAN 16.0f
#define INV_H ((float)NPTS / XSPAN)   /* 128 */
#define H_STEP (XSPAN / (float)NPTS)

// tokens = 32*4096 = 131072 ; per block 64 tokens, 256 threads (4 thr/token)
#define TOK_PER_BLK 64
#define THREADS 256
#define NBLK 2048
#define TILE_FLOATS (TOK_PER_BLK * NW)        /* 7552 */
#define OUT_PER_BLK (TOK_PER_BLK * NB)        /* 832 */
#define SMEM_FLOATS (TILE_FLOATS + OUT_PER_BLK + NB * MAXW)  /* 8540 -> 34.2KB */

// build kernel: serial per-entry math, 64 entries / 64 threads per block
#define ENT_PER_BLK 64
#define BUILD_THREADS 64

// Compile-time ragged structure (fixed by the problem)
__device__ constexpr int K_START[NB] = {5, 14, 23, 32, 41, 50, 59, 68, 77, 86, 95, 107, 115};
__device__ constexpr int K_LEN[NB]   = {9, 9, 9, 9, 9, 9, 9, 9, 9, 9, 12, 8, 3};

// Scratch (__device__ globals are the allowed scratch mechanism)
__device__ float g_table[NB * TAB_STRIDE];
__device__ float g_wts[NB * MAXW];

__device__ __forceinline__ float gelu_erf(float x) {
    return 0.5f * x * (1.0f + erff(x * 0.70710678118654752f));
}

// ---------------------------------------------------------------------------
// Kernel 1: build per-body tables (serial per-entry, small blocks to fill chip)
// grid = (ceil(TAB_STRIDE/64), 13), block = 64
// ---------------------------------------------------------------------------
__global__ __launch_bounds__(BUILD_THREADS) void build_table_kernel(
    const float* __restrict__ agg_logits,
    const float* __restrict__ W1, const float* __restrict__ b1,
    const float* __restrict__ W2, const float* __restrict__ b2,
    const float* __restrict__ W3, const float* __restrict__ b3,
    const float* __restrict__ W4, const float* __restrict__ b4)
{
    const int c   = blockIdx.y;
    const int tid = threadIdx.x;

    // Fused softmax: block (0,0), lanes 0..12 compute g_wts once.
    if (blockIdx.x == 0 && c == 0 && tid < NB) {
        const int cc = tid;
        const int L = K_LEN[cc];
        float tmp[MAXW];
        float mx = -1e30f;
        for (int k = 0; k < L; k++) {
            tmp[k] = agg_logits[cc * MAXW + k];
            mx = fmaxf(mx, tmp[k]);
        }
        float s = 0.0f;
        for (int k = 0; k < L; k++) { tmp[k] = expf(tmp[k] - mx); s += tmp[k]; }
        const float inv = 1.0f / s;
        for (int k = 0; k < MAXW; k++)
            g_wts[cc * MAXW + k] = (k < L) ? tmp[k] * inv : 0.0f;
    }

    __shared__ float sW1[32], sB1[32], sB2[64], sB3[32], sW4[32];
    __shared__ float sW2[32 * 64];   // [i][o] row-major, o contiguous
    __shared__ float sW3[64 * 32];
    __shared__ float sB4;

    // float4 weight staging (2048+2048 floats = 1024 float4, 64 threads)
    {
        const float4* w2 = reinterpret_cast<const float4*>(W2 + c * 2048);
        const float4* w3 = reinterpret_cast<const float4*>(W3 + c * 2048);
        float4* s2 = reinterpret_cast<float4*>(sW2);
        float4* s3 = reinterpret_cast<float4*>(sW3);
        for (int i = tid; i < 512; i += BUILD_THREADS) {
            s2[i] = w2[i];
            s3[i] = w3[i];
        }
    }
    if (tid < 32) {
        sW1[tid] = W1[c * 32 + tid];
        sB1[tid] = b1[c * 32 + tid];
        sB3[tid] = b3[c * 32 + tid];
        sW4[tid] = W4[c * 32 + tid];
        sB2[tid] = b2[c * 64 + tid];
        sB2[tid + 32] = b2[c * 64 + 32 + tid];
    }
    if (tid == 0) sB4 = b4[c];
    __syncthreads();

    const int i = blockIdx.x * ENT_PER_BLK + tid;
    if (i >= TAB_STRIDE) return;

    const float x = XMIN + H_STEP * (float)i;

    float h1[32];
#pragma unroll
    for (int j = 0; j < 32; j++)
        h1[j] = gelu_erf(fmaf(x, sW1[j], sB1[j]));

    float h2[64];
#pragma unroll
    for (int ob = 0; ob < 64; ob += 4) {
        float z0 = sB2[ob], z1 = sB2[ob + 1], z2 = sB2[ob + 2], z3 = sB2[ob + 3];
#pragma unroll
        for (int j = 0; j < 32; j++) {
            const float4 w = *reinterpret_cast<const float4*>(&sW2[j * 64 + ob]);
            z0 = fmaf(h1[j], w.x, z0);
            z1 = fmaf(h1[j], w.y, z1);
            z2 = fmaf(h1[j], w.z, z2);
            z3 = fmaf(h1[j], w.w, z3);
        }
        h2[ob]     = gelu_erf(z0);
        h2[ob + 1] = gelu_erf(z1);
        h2[ob + 2] = gelu_erf(z2);
        h2[ob + 3] = gelu_erf(z3);
    }

    float h3[32];
#pragma unroll
    for (int ob = 0; ob < 32; ob += 4) {
        float z0 = sB3[ob], z1 = sB3[ob + 1], z2 = sB3[ob + 2], z3 = sB3[ob + 3];
#pragma unroll
        for (int j = 0; j < 64; j++) {
            const float4 w = *reinterpret_cast<const float4*>(&sW3[j * 32 + ob]);
            z0 = fmaf(h2[j], w.x, z0);
            z1 = fmaf(h2[j], w.y, z1);
            z2 = fmaf(h2[j], w.z, z2);
            z3 = fmaf(h2[j], w.w, z3);
        }
        h3[ob]     = gelu_erf(z0);
        h3[ob + 1] = gelu_erf(z1);
        h3[ob + 2] = gelu_erf(z2);
        h3[ob + 3] = gelu_erf(z3);
    }

    float z = sB4;
#pragma unroll
    for (int j = 0; j < 32; j++)
        z = fmaf(h3[j], sW4[j], z);

    g_table[c * TAB_STRIDE + i] = tanhf(z);
}

// ---------------------------------------------------------------------------
// Templated per-thread body-range worker (fully unrolled at compile time)
// ---------------------------------------------------------------------------
template<int LO, int HI>
__device__ __forceinline__ void process_bodies(
    const float* __restrict__ x, const float* __restrict__ wts,
    float* __restrict__ so)
{
#pragma unroll
    for (int c = LO; c < HI; c++) {
        float acc = 0.0f;
        const int st = K_START[c];
#pragma unroll
        for (int k = 0; k < K_LEN[c]; k++)
            acc = fmaf(x[st + k], wts[c * MAXW + k], acc);

        float t = (acc - XMIN) * INV_H;
        t = fminf(fmaxf(t, 0.0f), (float)NPTS - 0.001f);
        const int   i0 = (int)t;
        const float fr = t - (float)i0;
        const float* tb = g_table + c * TAB_STRIDE + i0;
        const float v0 = __ldg(tb);
        const float v1 = __ldg(tb + 1);
        so[c] = fmaf(fr, v1 - v0, v0);
    }
}

// ---------------------------------------------------------------------------
// Kernel 2: stream wave_features, ragged weighted sums, table lerp, store.
// grid = 2048, block = 256, dynamic smem = SMEM_FLOATS*4 (34.2KB -> 6 CTA/SM)
// ---------------------------------------------------------------------------
__global__ __launch_bounds__(THREADS) void main_kernel(
    const float* __restrict__ wf,
    float* __restrict__ out)
{
    extern __shared__ float smem[];
    float* sx   = smem;                       // [64 * 118] flat, token-major
    float* sout = smem + TILE_FLOATS;         // [64 * 13]
    float* wts  = sout + OUT_PER_BLK;         // [13 * 12]

    const int tid = threadIdx.x;

    // Coalesced float4 tile load (7552 floats = 1888 float4 per block)
    {
        const float4* g4 = reinterpret_cast<const float4*>(wf) +
                           (size_t)blockIdx.x * (TILE_FLOATS / 4);
        float4* s4 = reinterpret_cast<float4*>(sx);
        for (int i = tid; i < TILE_FLOATS / 4; i += THREADS)
            s4[i] = g4[i];
    }

    // Softmax weights: 156 floats, one pass (THREADS=256 > 156)
    if (tid < NB * MAXW) wts[tid] = g_wts[tid];
    __syncthreads();

    // 4 threads per token: grp selects a compile-time body range
    const int tok = tid & (TOK_PER_BLK - 1);
    const int grp = tid >> 6;
    const float* x = sx + tok * NW;
    float* so = sout + tok * NB;

    switch (grp) {
        case 0: process_bodies<0, 3>(x, wts, so);  break;
        case 1: process_bodies<3, 6>(x, wts, so);  break;
        case 2: process_bodies<6, 9>(x, wts, so);  break;
        default: process_bodies<9, 13>(x, wts, so); break;
    }
    __syncthreads();

    // Coalesced float4 output store: 832 floats = 208 float4 per block
    float4* ob4 = reinterpret_cast<float4*>(out + (size_t)blockIdx.x * OUT_PER_BLK);
    const float4* so4 = reinterpret_cast<const float4*>(sout);
    if (tid < OUT_PER_BLK / 4)
        ob4[tid] = so4[tid];
}

// ---------------------------------------------------------------------------
extern "C" void kernel_launch(void* const* d_in, const int* in_sizes, int n_in,
                              void* d_out, int out_size)
{
    const float* wf  = (const float*)d_in[0];
    const float* lg  = (const float*)d_in[1];
    const float* W1  = (const float*)d_in[2];
    const float* b1  = (const float*)d_in[3];
    const float* W2  = (const float*)d_in[4];
    const float* b2  = (const float*)d_in[5];
    const float* W3  = (const float*)d_in[6];
    const float* b3  = (const float*)d_in[7];
    const float* W4  = (const float*)d_in[8];
    const float* b4  = (const float*)d_in[9];
    float* out = (float*)d_out;

    (void)cudaFuncSetAttribute(main_kernel,
                               cudaFuncAttributeMaxDynamicSharedMemorySize,
                               SMEM_FLOATS * 4);

    dim3 bgrid((TAB_STRIDE + ENT_PER_BLK - 1) / ENT_PER_BLK, NB);
    build_table_kernel<<<bgrid, BUILD_THREADS>>>(lg, W1, b1, W2, b2, W3, b3, W4, b4);

    main_kernel<<<NBLK, THREADS, SMEM_FLOATS * 4>>>(wf, out);

    (void)in_sizes; (void)n_in; (void)out_size;
}

// round 12
// speedup vs baseline: 1.4884x; 1.0031x over previous
#include <cuda_runtime.h>
#include <math.h>

#define NB 13
#define NW 118
#define MAXW 12
#define NPTS 1024
#define TAB_STRIDE (NPTS + 1)
#define XMIN (-8.0f)
#define XSPAN 16.0f
#define INV_H ((float)NPTS / XSPAN)   /* 64 */
#define H_STEP (XSPAN / (float)NPTS)

// tokens = 32*4096 = 131072 ; per block 64 tokens, 256 threads (4 thr/token)
#define TOK_PER_BLK 64
#define THREADS 256
#define NBLK 2048
#define TILE_FLOATS (TOK_PER_BLK * NW)        /* 7552 */
#define OUT_PER_BLK (TOK_PER_BLK * NB)        /* 832 */
#define SMEM_FLOATS (TILE_FLOATS + OUT_PER_BLK + NB * MAXW)  /* 8540 -> 34.2KB */

// Compile-time ragged structure (fixed by the problem)
__device__ constexpr int K_START[NB] = {5, 14, 23, 32, 41, 50, 59, 68, 77, 86, 95, 107, 115};
__device__ constexpr int K_LEN[NB]   = {9, 9, 9, 9, 9, 9, 9, 9, 9, 9, 12, 8, 3};

// Scratch (__device__ globals are the allowed scratch mechanism)
__device__ float g_table[NB * TAB_STRIDE];
__device__ float g_wts[NB * MAXW];

__device__ __forceinline__ float gelu_erf(float x) {
    return 0.5f * x * (1.0f + erff(x * 0.70710678118654752f));
}

// ---------------------------------------------------------------------------
// Kernel 1: build per-body tables (serial per-entry, R7-proven shape).
// grid = (ceil(TAB_STRIDE/256), 13), block = 256
// ---------------------------------------------------------------------------
__global__ __launch_bounds__(256) void build_table_kernel(
    const float* __restrict__ agg_logits,
    const float* __restrict__ W1, const float* __restrict__ b1,
    const float* __restrict__ W2, const float* __restrict__ b2,
    const float* __restrict__ W3, const float* __restrict__ b3,
    const float* __restrict__ W4, const float* __restrict__ b4)
{
    const int c   = blockIdx.y;
    const int tid = threadIdx.x;

    // Fused softmax: block (0,0), lanes 0..12 compute g_wts once.
    if (blockIdx.x == 0 && c == 0 && tid < NB) {
        const int cc = tid;
        const int L = K_LEN[cc];
        float tmp[MAXW];
        float mx = -1e30f;
        for (int k = 0; k < L; k++) {
            tmp[k] = agg_logits[cc * MAXW + k];
            mx = fmaxf(mx, tmp[k]);
        }
        float s = 0.0f;
        for (int k = 0; k < L; k++) { tmp[k] = expf(tmp[k] - mx); s += tmp[k]; }
        const float inv = 1.0f / s;
        for (int k = 0; k < MAXW; k++)
            g_wts[cc * MAXW + k] = (k < L) ? tmp[k] * inv : 0.0f;
    }

    __shared__ float sW1[32], sB1[32], sB2[64], sB3[32], sW4[32];
    __shared__ float sW2[32 * 64];   // [i][o] row-major, o contiguous
    __shared__ float sW3[64 * 32];
    __shared__ float sB4;

    for (int i = tid; i < 2048; i += 256) {
        sW2[i] = W2[c * 2048 + i];
        sW3[i] = W3[c * 2048 + i];
    }
    if (tid < 32) {
        sW1[tid] = W1[c * 32 + tid];
        sB1[tid] = b1[c * 32 + tid];
        sB3[tid] = b3[c * 32 + tid];
        sW4[tid] = W4[c * 32 + tid];
    }
    if (tid < 64) sB2[tid] = b2[c * 64 + tid];
    if (tid == 0) sB4 = b4[c];
    __syncthreads();

    const int i = blockIdx.x * 256 + tid;
    if (i >= TAB_STRIDE) return;

    const float x = XMIN + H_STEP * (float)i;

    float h1[32];
#pragma unroll
    for (int j = 0; j < 32; j++)
        h1[j] = gelu_erf(fmaf(x, sW1[j], sB1[j]));

    float h2[64];
#pragma unroll
    for (int ob = 0; ob < 64; ob += 4) {
        float z0 = sB2[ob], z1 = sB2[ob + 1], z2 = sB2[ob + 2], z3 = sB2[ob + 3];
#pragma unroll
        for (int j = 0; j < 32; j++) {
            const float4 w = *reinterpret_cast<const float4*>(&sW2[j * 64 + ob]);
            z0 = fmaf(h1[j], w.x, z0);
            z1 = fmaf(h1[j], w.y, z1);
            z2 = fmaf(h1[j], w.z, z2);
            z3 = fmaf(h1[j], w.w, z3);
        }
        h2[ob]     = gelu_erf(z0);
        h2[ob + 1] = gelu_erf(z1);
        h2[ob + 2] = gelu_erf(z2);
        h2[ob + 3] = gelu_erf(z3);
    }

    float h3[32];
#pragma unroll
    for (int ob = 0; ob < 32; ob += 4) {
        float z0 = sB3[ob], z1 = sB3[ob + 1], z2 = sB3[ob + 2], z3 = sB3[ob + 3];
#pragma unroll
        for (int j = 0; j < 64; j++) {
            const float4 w = *reinterpret_cast<const float4*>(&sW3[j * 32 + ob]);
            z0 = fmaf(h2[j], w.x, z0);
            z1 = fmaf(h2[j], w.y, z1);
            z2 = fmaf(h2[j], w.z, z2);
            z3 = fmaf(h2[j], w.w, z3);
        }
        h3[ob]     = gelu_erf(z0);
        h3[ob + 1] = gelu_erf(z1);
        h3[ob + 2] = gelu_erf(z2);
        h3[ob + 3] = gelu_erf(z3);
    }

    float z = sB4;
#pragma unroll
    for (int j = 0; j < 32; j++)
        z = fmaf(h3[j], sW4[j], z);

    g_table[c * TAB_STRIDE + i] = tanhf(z);
}

// ---------------------------------------------------------------------------
// Templated per-thread body-range worker (fully unrolled at compile time)
// ---------------------------------------------------------------------------
template<int LO, int HI>
__device__ __forceinline__ void process_bodies(
    const float* __restrict__ x, const float* __restrict__ wts,
    float* __restrict__ so)
{
#pragma unroll
    for (int c = LO; c < HI; c++) {
        float acc = 0.0f;
        const int st = K_START[c];
#pragma unroll
        for (int k = 0; k < K_LEN[c]; k++)
            acc = fmaf(x[st + k], wts[c * MAXW + k], acc);

        float t = (acc - XMIN) * INV_H;
        t = fminf(fmaxf(t, 0.0f), (float)NPTS - 0.001f);
        const int   i0 = (int)t;
        const float fr = t - (float)i0;
        const float* tb = g_table + c * TAB_STRIDE + i0;
        const float v0 = __ldg(tb);
        const float v1 = __ldg(tb + 1);
        so[c] = fmaf(fr, v1 - v0, v0);
    }
}

// ---------------------------------------------------------------------------
// Kernel 2: stream wave_features, ragged weighted sums, table lerp, store.
// grid = 2048, block = 256, dynamic smem = SMEM_FLOATS*4 (34.2KB -> 6 CTA/SM)
// ---------------------------------------------------------------------------
__global__ __launch_bounds__(THREADS) void main_kernel(
    const float* __restrict__ wf,
    float* __restrict__ out)
{
    extern __shared__ float smem[];
    float* sx   = smem;                       // [64 * 118] flat, token-major
    float* sout = smem + TILE_FLOATS;         // [64 * 13]
    float* wts  = sout + OUT_PER_BLK;         // [13 * 12]

    const int tid = threadIdx.x;

    // Coalesced float4 tile load (7552 floats = 1888 float4 per block)
    {
        const float4* g4 = reinterpret_cast<const float4*>(wf) +
                           (size_t)blockIdx.x * (TILE_FLOATS / 4);
        float4* s4 = reinterpret_cast<float4*>(sx);
        for (int i = tid; i < TILE_FLOATS / 4; i += THREADS)
            s4[i] = g4[i];
    }

    // Softmax weights: 156 floats, one pass (THREADS=256 > 156)
    if (tid < NB * MAXW) wts[tid] = g_wts[tid];
    __syncthreads();

    // 4 threads per token: grp selects a compile-time body range
    const int tok = tid & (TOK_PER_BLK - 1);
    const int grp = tid >> 6;
    const float* x = sx + tok * NW;
    float* so = sout + tok * NB;

    switch (grp) {
        case 0: process_bodies<0, 3>(x, wts, so);  break;
        case 1: process_bodies<3, 6>(x, wts, so);  break;
        case 2: process_bodies<6, 9>(x, wts, so);  break;
        default: process_bodies<9, 13>(x, wts, so); break;
    }
    __syncthreads();

    // Coalesced float4 output store: 832 floats = 208 float4 per block
    float4* ob4 = reinterpret_cast<float4*>(out + (size_t)blockIdx.x * OUT_PER_BLK);
    const float4* so4 = reinterpret_cast<const float4*>(sout);
    if (tid < OUT_PER_BLK / 4)
        ob4[tid] = so4[tid];
}

// ---------------------------------------------------------------------------
extern "C" void kernel_launch(void* const* d_in, const int* in_sizes, int n_in,
                              void* d_out, int out_size)
{
    const float* wf  = (const float*)d_in[0];
    const float* lg  = (const float*)d_in[1];
    const float* W1  = (const float*)d_in[2];
    const float* b1  = (const float*)d_in[3];
    const float* W2  = (const float*)d_in[4];
    const float* b2  = (const float*)d_in[5];
    const float* W3  = (const float*)d_in[6];
    const float* b3  = (const float*)d_in[7];
    const float* W4  = (const float*)d_in[8];
    const float* b4  = (const float*)d_in[9];
    float* out = (float*)d_out;

    (void)cudaFuncSetAttribute(main_kernel,
                               cudaFuncAttributeMaxDynamicSharedMemorySize,
                               SMEM_FLOATS * 4);

    dim3 bgrid((TAB_STRIDE + 255) / 256, NB);
    build_table_kernel<<<bgrid, 256>>>(lg, W1, b1, W2, b2, W3, b3, W4, b4);

    main_kernel<<<NBLK, THREADS, SMEM_FLOATS * 4>>>(wf, out);

    (void)in_sizes; (void)n_in; (void)out_size;
}

// round 15
// speedup vs baseline: 1.6324x; 1.0968x over previous
#include <cuda_runtime.h>
#include <cstdint>
#include <math.h>

#define NB 13
#define NW 118
#define MAXW 12
#define NPTS 2048
#define TAB_STRIDE (NPTS + 1)
#define XMIN (-8.0f)
#define XSPAN 16.0f
#define INV_H ((float)NPTS / XSPAN)   /* 128 */
#define H_STEP (XSPAN / (float)NPTS)

// tokens = 32*4096 = 131072 ; per block 32 tokens, 128 threads (4 thr/token)
#define TOK_PER_BLK 32
#define THREADS 128
#define NBLK 4096
#define TILE_FLOATS (TOK_PER_BLK * NW)        /* 3776 */
#define OUT_PER_BLK (TOK_PER_BLK * NB)        /* 416 */
#define SMEM_FLOATS (TILE_FLOATS + OUT_PER_BLK + NB * MAXW)  /* 4348 -> 17.4KB */

// Compile-time ragged structure (fixed by the problem)
__device__ constexpr int K_START[NB] = {5, 14, 23, 32, 41, 50, 59, 68, 77, 86, 95, 107, 115};
__device__ constexpr int K_LEN[NB]   = {9, 9, 9, 9, 9, 9, 9, 9, 9, 9, 12, 8, 3};

// Scratch (__device__ globals are the allowed scratch mechanism)
__device__ float g_table[NB * TAB_STRIDE];
__device__ float g_wts[NB * MAXW];

__device__ __forceinline__ float gelu_erf(float x) {
    return 0.5f * x * (1.0f + erff(x * 0.70710678118654752f));
}

__device__ __forceinline__ unsigned int smem_u32(const void* p) {
    return (unsigned int)__cvta_generic_to_shared(p);
}

// ---------------------------------------------------------------------------
// Kernel 1: build per-body tables (serial per-entry, proven shape).
// grid = (ceil(TAB_STRIDE/256), 13), block = 256
// ---------------------------------------------------------------------------
__global__ __launch_bounds__(256) void build_table_kernel(
    const float* __restrict__ agg_logits,
    const float* __restrict__ W1, const float* __restrict__ b1,
    const float* __restrict__ W2, const float* __restrict__ b2,
    const float* __restrict__ W3, const float* __restrict__ b3,
    const float* __restrict__ W4, const float* __restrict__ b4)
{
    const int c   = blockIdx.y;
    const int tid = threadIdx.x;

    // Fused softmax: block (0,0), lanes 0..12 compute g_wts once.
    if (blockIdx.x == 0 && c == 0 && tid < NB) {
        const int cc = tid;
        const int L = K_LEN[cc];
        float tmp[MAXW];
        float mx = -1e30f;
        for (int k = 0; k < L; k++) {
            tmp[k] = agg_logits[cc * MAXW + k];
            mx = fmaxf(mx, tmp[k]);
        }
        float s = 0.0f;
        for (int k = 0; k < L; k++) { tmp[k] = expf(tmp[k] - mx); s += tmp[k]; }
        const float inv = 1.0f / s;
        for (int k = 0; k < MAXW; k++)
            g_wts[cc * MAXW + k] = (k < L) ? tmp[k] * inv : 0.0f;
    }

    __shared__ float sW1[32], sB1[32], sB2[64], sB3[32], sW4[32];
    __shared__ float sW2[32 * 64];   // [i][o] row-major, o contiguous
    __shared__ float sW3[64 * 32];
    __shared__ float sB4;

    for (int i = tid; i < 2048; i += 256) {
        sW2[i] = W2[c * 2048 + i];
        sW3[i] = W3[c * 2048 + i];
    }
    if (tid < 32) {
        sW1[tid] = W1[c * 32 + tid];
        sB1[tid] = b1[c * 32 + tid];
        sB3[tid] = b3[c * 32 + tid];
        sW4[tid] = W4[c * 32 + tid];
    }
    if (tid < 64) sB2[tid] = b2[c * 64 + tid];
    if (tid == 0) sB4 = b4[c];
    __syncthreads();

    const int i = blockIdx.x * 256 + tid;
    if (i >= TAB_STRIDE) return;

    const float x = XMIN + H_STEP * (float)i;

    float h1[32];
#pragma unroll
    for (int j = 0; j < 32; j++)
        h1[j] = gelu_erf(fmaf(x, sW1[j], sB1[j]));

    float h2[64];
#pragma unroll
    for (int ob = 0; ob < 64; ob += 4) {
        float z0 = sB2[ob], z1 = sB2[ob + 1], z2 = sB2[ob + 2], z3 = sB2[ob + 3];
#pragma unroll
        for (int j = 0; j < 32; j++) {
            const float4 w = *reinterpret_cast<const float4*>(&sW2[j * 64 + ob]);
            z0 = fmaf(h1[j], w.x, z0);
            z1 = fmaf(h1[j], w.y, z1);
            z2 = fmaf(h1[j], w.z, z2);
            z3 = fmaf(h1[j], w.w, z3);
        }
        h2[ob]     = gelu_erf(z0);
        h2[ob + 1] = gelu_erf(z1);
        h2[ob + 2] = gelu_erf(z2);
        h2[ob + 3] = gelu_erf(z3);
    }

    float h3[32];
#pragma unroll
    for (int ob = 0; ob < 32; ob += 4) {
        float z0 = sB3[ob], z1 = sB3[ob + 1], z2 = sB3[ob + 2], z3 = sB3[ob + 3];
#pragma unroll
        for (int j = 0; j < 64; j++) {
            const float4 w = *reinterpret_cast<const float4*>(&sW3[j * 32 + ob]);
            z0 = fmaf(h2[j], w.x, z0);
            z1 = fmaf(h2[j], w.y, z1);
            z2 = fmaf(h2[j], w.z, z2);
            z3 = fmaf(h2[j], w.w, z3);
        }
        h3[ob]     = gelu_erf(z0);
        h3[ob + 1] = gelu_erf(z1);
        h3[ob + 2] = gelu_erf(z2);
        h3[ob + 3] = gelu_erf(z3);
    }

    float z = sB4;
#pragma unroll
    for (int j = 0; j < 32; j++)
        z = fmaf(h3[j], sW4[j], z);

    g_table[c * TAB_STRIDE + i] = tanhf(z);
}

// ---------------------------------------------------------------------------
// Templated per-thread body-range worker (fully unrolled at compile time)
// ---------------------------------------------------------------------------
template<int LO, int HI>
__device__ __forceinline__ void process_bodies(
    const float* __restrict__ x, const float* __restrict__ wts,
    float* __restrict__ so)
{
#pragma unroll
    for (int c = LO; c < HI; c++) {
        float acc = 0.0f;
        const int st = K_START[c];
#pragma unroll
        for (int k = 0; k < K_LEN[c]; k++)
            acc = fmaf(x[st + k], wts[c * MAXW + k], acc);

        float t = (acc - XMIN) * INV_H;
        t = fminf(fmaxf(t, 0.0f), (float)NPTS - 0.001f);
        const int   i0 = (int)t;
        const float fr = t - (float)i0;
        const float* tb = g_table + c * TAB_STRIDE + i0;
        const float v0 = __ldg(tb);
        const float v1 = __ldg(tb + 1);
        so[c] = fmaf(fr, v1 - v0, v0);
    }
}

// ---------------------------------------------------------------------------
// Kernel 2: stream wave_features via cp.async, ragged sums, table lerp, store.
// grid = 4096, block = 128, dynamic smem = SMEM_FLOATS*4 (17.4KB -> 13 CTA/SM)
// ---------------------------------------------------------------------------
__global__ __launch_bounds__(THREADS) void main_kernel(
    const float* __restrict__ wf,
    float* __restrict__ out)
{
    extern __shared__ float smem[];
    float* sx   = smem;                       // [32 * 118] flat, token-major
    float* sout = smem + TILE_FLOATS;         // [32 * 13]
    float* wts  = sout + OUT_PER_BLK;         // [13 * 12]

    const int tid = threadIdx.x;

    // Async tile stage: 3776 floats = 944 x 16B cp.async, no register roundtrip
    {
        const float4* g4 = reinterpret_cast<const float4*>(wf) +
                           (size_t)blockIdx.x * (TILE_FLOATS / 4);
        unsigned int sbase = smem_u32(sx);
#pragma unroll 2
        for (int i = tid; i < TILE_FLOATS / 4; i += THREADS) {
            asm volatile("cp.async.cg.shared.global [%0], [%1], 16;\n"
                         :: "r"(sbase + i * 16), "l"(g4 + i));
        }
        asm volatile("cp.async.commit_group;\n");
    }

    // Softmax weights while the tile is in flight (156 floats, strided: 128 thr)
    for (int i = tid; i < NB * MAXW; i += THREADS)
        wts[i] = g_wts[i];

    asm volatile("cp.async.wait_group 0;\n" ::: "memory");
    __syncthreads();

    // 4 threads per token: grp selects a compile-time body range
    const int tok = tid & (TOK_PER_BLK - 1);
    const int grp = tid >> 5;
    const float* x = sx + tok * NW;
    float* so = sout + tok * NB;

    switch (grp) {
        case 0: process_bodies<0, 3>(x, wts, so);  break;
        case 1: process_bodies<3, 6>(x, wts, so);  break;
        case 2: process_bodies<6, 9>(x, wts, so);  break;
        default: process_bodies<9, 13>(x, wts, so); break;
    }
    __syncthreads();

    // Coalesced float4 output store: 416 floats = 104 float4 per block
    float4* ob4 = reinterpret_cast<float4*>(out + (size_t)blockIdx.x * OUT_PER_BLK);
    const float4* so4 = reinterpret_cast<const float4*>(sout);
    if (tid < OUT_PER_BLK / 4)
        ob4[tid] = so4[tid];
}

// ---------------------------------------------------------------------------
extern "C" void kernel_launch(void* const* d_in, const int* in_sizes, int n_in,
                              void* d_out, int out_size)
{
    const float* wf  = (const float*)d_in[0];
    const float* lg  = (const float*)d_in[1];
    const float* W1  = (const float*)d_in[2];
    const float* b1  = (const float*)d_in[3];
    const float* W2  = (const float*)d_in[4];
    const float* b2  = (const float*)d_in[5];
    const float* W3  = (const float*)d_in[6];
    const float* b3  = (const float*)d_in[7];
    const float* W4  = (const float*)d_in[8];
    const float* b4  = (const float*)d_in[9];
    float* out = (float*)d_out;

    (void)cudaFuncSetAttribute(main_kernel,
                               cudaFuncAttributeMaxDynamicSharedMemorySize,
                               SMEM_FLOATS * 4);

    dim3 bgrid((TAB_STRIDE + 255) / 256, NB);
    build_table_kernel<<<bgrid, 256>>>(lg, W1, b1, W2, b2, W3, b3, W4, b4);

    main_kernel<<<NBLK, THREADS, SMEM_FLOATS * 4>>>(wf, out);

    (void)in_sizes; (void)n_in; (void)out_size;
}